// round 11
// baseline (speedup 1.0000x reference)
#include <cuda_runtime.h>
#include <math.h>

#define NROWS   65536
#define DIM     64
#define KC      512
#define NQ      (NROWS*DIM)
#define THREADS 512
#define MTILE   64
#define NTILES  (NROWS/MTILE)    // 1024
#define GRID    148
#define XTS2    136              // dup-X row stride in floats (128 + 8 pad)

// smem byte offsets
#define SMO_ET   0                        // E^T: 64 x 512 f32 = 131072 B
#define SMO_XT   131072                   // XTd2: 64 x 136 f32 = 34816 B
#define SMO_SB   165888                   // 512 f32 code norms
#define SMO_SA   167936                   // 64 f32 row norms
#define SMO_KEYS 168192                   // 64 u64 argmin keys
#define SMEM_TOTAL 168704

// Output: [0] loss | [1..NQ] quantized_st (base out+1, 4B-aligned) |
//         [1+NQ] perplexity | [2+NQ..] indices (as float)

typedef unsigned long long ull;

__device__ float  g_ET[DIM*KC];     // E^T [d][k]
__device__ float  g_sb[KC];
__device__ int    g_hist[KC];
__device__ double g_sse;
__device__ unsigned g_done;

__device__ __forceinline__ void upk2(ull v, float& lo, float& hi) {
    asm("mov.b64 {%0, %1}, %2;" : "=f"(lo), "=f"(hi) : "l"(v));
}
__device__ __forceinline__ ull fma2(ull a, ull b, ull c) {
    ull d; asm("fma.rn.f32x2 %0, %1, %2, %3;" : "=l"(d) : "l"(a), "l"(b), "l"(c));
    return d;
}
// order-preserving float -> u32 (total order) for (dd, k) min keys
__device__ __forceinline__ unsigned ord32(float f) {
    unsigned u = __float_as_uint(f);
    return (u & 0x80000000u) ? ~u : (u | 0x80000000u);
}

// ---- prep: E^T image + exact code norms + zero globals ----------------------
__global__ void prep_kernel(const float* __restrict__ emb) {
    int k = blockIdx.x * blockDim.x + threadIdx.x;
    if (k >= KC) return;
    if (k == 0) { g_sse = 0.0; g_done = 0u; }
    g_hist[k] = 0;

    const float* e = emb + (size_t)k * DIM;
    float b0 = 0.f, b1 = 0.f;
    #pragma unroll
    for (int i = 0; i < DIM; i += 2) {
        b0 = fmaf(e[i],     e[i],     b0);
        b1 = fmaf(e[i + 1], e[i + 1], b1);
    }
    g_sb[k] = b0 + b1;
    #pragma unroll
    for (int d = 0; d < DIM; d++)
        g_ET[d * KC + k] = e[d];
}

// -----------------------------------------------------------------------------
// Persistent GEMM-tiled VQ: 64-row x 512-code tiles, 512 threads,
// 8 rows x 4 code-pairs per thread. Code-pair packing (natural ull loads from
// E^T) + x-splats materialized from a duplicated X layout -> zero splat MOVs.
// Exact JAX argmin: d_k = fl( fl(A + b_k) - 2*c_k ), first-index tie via
// (dd,k) min-key.
// -----------------------------------------------------------------------------
__global__ void __launch_bounds__(THREADS, 1)
vq_gemm_kernel(const float* __restrict__ inp,
               const float* __restrict__ emb,
               float* __restrict__ out)
{
    extern __shared__ char smc[];
    float* ET   = reinterpret_cast<float*>(smc + SMO_ET);
    float* XT   = reinterpret_cast<float*>(smc + SMO_XT);   // dup layout
    float* sbv  = reinterpret_cast<float*>(smc + SMO_SB);
    float* sA   = reinterpret_cast<float*>(smc + SMO_SA);
    ull*   keys = reinterpret_cast<ull*>(smc + SMO_KEYS);

    const int tid  = threadIdx.x;
    const int lane = tid & 31;
    const int cp   = tid & 63;    // code-pair lane: pairs cp + 64*j
    const int rg   = tid >> 6;    // row-group 0..7 (8 rows each)
    const int prow = tid >> 3;    // pro/epilogue: row 0..63
    const int part = tid & 7;     //               8 threads per row

    // one-time smem fill: E^T + code norms
    for (int i = tid; i < DIM * KC / 4; i += THREADS)
        reinterpret_cast<float4*>(ET)[i] =
            reinterpret_cast<const float4*>(g_ET)[i];
    for (int i = tid; i < KC; i += THREADS) sbv[i] = g_sb[i];

    for (int tile = blockIdx.x; tile < NTILES; tile += GRID) {
        __syncthreads();   // prior tile reads done (first iter: ET fill)

        // ---- prologue (all threads, 8 per row): dup-X store + row norm -----
        {
            const float4* xp = reinterpret_cast<const float4*>(
                inp + (size_t)(tile * MTILE + prow) * DIM + part * 8);
            float4 v0 = xp[0], v1 = xp[1];
            float a = 0.f;
            a = fmaf(v0.x, v0.x, a); a = fmaf(v0.y, v0.y, a);
            a = fmaf(v0.z, v0.z, a); a = fmaf(v0.w, v0.w, a);
            a = fmaf(v1.x, v1.x, a); a = fmaf(v1.y, v1.y, a);
            a = fmaf(v1.z, v1.z, a); a = fmaf(v1.w, v1.w, a);
            // A order differs from row-serial; argmin-invariant (ULP(64) grid)
            a += __shfl_xor_sync(0xFFFFFFFFu, a, 1, 8);
            a += __shfl_xor_sync(0xFFFFFFFFu, a, 2, 8);
            a += __shfl_xor_sync(0xFFFFFFFFu, a, 4, 8);

            float4* xd = reinterpret_cast<float4*>(
                XT + prow * XTS2 + part * 16);
            xd[0] = make_float4(v0.x, v0.x, v0.y, v0.y);
            xd[1] = make_float4(v0.z, v0.z, v0.w, v0.w);
            xd[2] = make_float4(v1.x, v1.x, v1.y, v1.y);
            xd[3] = make_float4(v1.z, v1.z, v1.w, v1.w);
            if (part == 0) sA[prow] = a;
            if (tid < MTILE) keys[tid] = ~0ull;
        }
        __syncthreads();

        // ---- mainloop: acc[i][j] = c(row rg*8+i, codes 2(cp+64j),+1) -------
        ull acc[8][4];
        #pragma unroll
        for (int i = 0; i < 8; i++)
            #pragma unroll
            for (int j = 0; j < 4; j++) acc[i][j] = 0ull;

        const float* xr  = XT + rg * 8 * XTS2;
        const float* ETc = ET + 2 * cp;
        #pragma unroll 2
        for (int d2 = 0; d2 < DIM / 2; d2++) {
            const float* Ed = ETc + (2 * d2) * KC;
            ull e0[4], e1[4];
            #pragma unroll
            for (int j = 0; j < 4; j++) {
                e0[j] = *reinterpret_cast<const ull*>(Ed + 128 * j);       // d
                e1[j] = *reinterpret_cast<const ull*>(Ed + KC + 128 * j);  // d+1
            }
            #pragma unroll
            for (int ih = 0; ih < 2; ih++) {           // row halves: regs
                ulonglong2 xs[4];
                #pragma unroll
                for (int i = 0; i < 4; i++)            // bcast LDS.128:
                    xs[i] = *reinterpret_cast<const ulonglong2*>(
                        xr + (ih * 4 + i) * XTS2 + 4 * d2);  // {dup d, dup d+1}
                #pragma unroll
                for (int i = 0; i < 4; i++) {
                    int r = ih * 4 + i;
                    acc[r][0] = fma2(xs[i].x, e0[0], acc[r][0]);
                    acc[r][1] = fma2(xs[i].x, e0[1], acc[r][1]);
                    acc[r][2] = fma2(xs[i].x, e0[2], acc[r][2]);
                    acc[r][3] = fma2(xs[i].x, e0[3], acc[r][3]);
                    acc[r][0] = fma2(xs[i].y, e1[0], acc[r][0]);
                    acc[r][1] = fma2(xs[i].y, e1[1], acc[r][1]);
                    acc[r][2] = fma2(xs[i].y, e1[2], acc[r][2]);
                    acc[r][3] = fma2(xs[i].y, e1[3], acc[r][3]);
                }
            }
        }

        // ---- per-row argmin keys over this thread's 8 codes ----------------
        float b0[4], b1[4];
        #pragma unroll
        for (int j = 0; j < 4; j++) {
            int k0 = 2 * (cp + 64 * j);
            b0[j] = sbv[k0];
            b1[j] = sbv[k0 + 1];
        }
        #pragma unroll
        for (int i = 0; i < 8; i++) {
            float tA = sA[rg * 8 + i];
            ull best = ~0ull;
            #pragma unroll
            for (int j = 0; j < 4; j++) {
                int k0 = 2 * (cp + 64 * j);
                float c0, c1;
                upk2(acc[i][j], c0, c1);
                float dd0 = (tA + b0[j]) - 2.0f * c0;   // fl(fl(A+b)-2c)
                ull  key0 = ((ull)ord32(dd0) << 32) | (unsigned)k0;
                if (key0 < best) best = key0;
                float dd1 = (tA + b1[j]) - 2.0f * c1;
                ull  key1 = ((ull)ord32(dd1) << 32) | (unsigned)(k0 + 1);
                if (key1 < best) best = key1;
            }
            #pragma unroll
            for (int off = 16; off > 0; off >>= 1) {
                ull o = __shfl_xor_sync(0xFFFFFFFFu, best, off);
                best = (o < best) ? o : best;
            }
            if (lane == 0) atomicMin(&keys[rg * 8 + i], best);
        }
        __syncthreads();

        // ---- epilogue (all threads, 8 per row) ------------------------------
        {
            const int row = tile * MTILE + prow;
            const int bik = (int)(unsigned)(keys[prow] & 0xFFFFFFFFull);

            if (part == 0) {
                out[2 + NQ + row] = (float)bik;
                atomicAdd(&g_hist[bik], 1);
            }
            const float4* xp = reinterpret_cast<const float4*>(
                inp + (size_t)row * DIM + part * 8);
            const float4* ep = reinterpret_cast<const float4*>(
                emb + (size_t)bik * DIM + part * 8);
            float* q = out + 1 + (size_t)row * DIM + part * 8;  // 4B-aligned

            float sse = 0.f;
            #pragma unroll
            for (int i = 0; i < 2; i++) {
                float4 xv = xp[i], ev = ep[i];
                float d0 = ev.x - xv.x, d1 = ev.y - xv.y;
                float d2 = ev.z - xv.z, d3 = ev.w - xv.w;
                q[4*i+0] = xv.x + d0;                 // fl(x + fl(q-x))
                q[4*i+1] = xv.y + d1;
                q[4*i+2] = xv.z + d2;
                q[4*i+3] = xv.w + d3;
                sse += d0*d0 + d1*d1 + d2*d2 + d3*d3;
            }
            sse += __shfl_xor_sync(0xFFFFFFFFu, sse, 1, 8);
            sse += __shfl_xor_sync(0xFFFFFFFFu, sse, 2, 8);
            sse += __shfl_xor_sync(0xFFFFFFFFu, sse, 4, 8);
            if (part == 0) atomicAdd(&g_sse, (double)sse);
        }
    }

    // ---- last CTA finalizes loss & perplexity -------------------------------
    __threadfence();
    __syncthreads();
    __shared__ unsigned s_last;
    if (tid == 0)
        s_last = (atomicAdd(&g_done, 1u) == GRID - 1u) ? 1u : 0u;
    __syncthreads();
    if (s_last) {
        __threadfence();
        __shared__ float red[THREADS];
        float acc = 0.f;
        for (int b = tid; b < KC; b += THREADS) {
            float pb = (float)g_hist[b] * (1.0f / (float)NROWS);
            acc += pb * logf(pb + 1e-10f);
        }
        red[tid] = acc;
        __syncthreads();
        for (int off = THREADS / 2; off > 0; off >>= 1) {
            if (tid < off) red[tid] += red[tid + off];
            __syncthreads();
        }
        if (tid == 0) {
            out[0]      = (float)(1.25 * (g_sse * (1.0 / (double)NQ)));
            out[1 + NQ] = expf(-red[0]);
        }
    }
}

extern "C" void kernel_launch(void* const* d_in, const int* in_sizes, int n_in,
                              void* d_out, int out_size)
{
    const float* inp = (const float*)d_in[0];
    const float* emb = (const float*)d_in[1];
    if (n_in >= 2 && in_sizes[0] == KC * DIM) {
        const float* t = inp; inp = emb; emb = t;
    }
    float* out = (float*)d_out;

    cudaFuncSetAttribute(vq_gemm_kernel,
                         cudaFuncAttributeMaxDynamicSharedMemorySize,
                         SMEM_TOTAL);

    prep_kernel<<<4, 128>>>(emb);
    vq_gemm_kernel<<<GRID, THREADS, SMEM_TOTAL>>>(inp, emb, out);
}